// round 7
// baseline (speedup 1.0000x reference)
#include <cuda_runtime.h>
#include <cstdint>

typedef unsigned long long u64;
typedef unsigned int u32;

#define NMAX      250048
#define PRE_NMS   6000
#define POST_NMS  300
#define CAP       32768
#define IOU_THR   0.7f
#define IMG_H     1024.0f
#define IMG_W     1024.0f
#define STRIDE_F  16.0f
#define MCH       1024
#define MWORDS    16
#define GRID      128
#define BLK       1024
#define NTHREADS  (GRID * BLK)      // 131072
#define NWARPS    (NTHREADS / 32)   // 4096

// ---------------- device scratch (static, zero-init; self-cleaning per run) ----------------
__device__ u32    g_hist[65536];
__device__ u32    g_t16;
__device__ u32    g_candCount;
__device__ u32    g_score32[NMAX];
__device__ u64    g_cand[CAP];
__device__ u32    g_rank[CAP];
__device__ float4 g_sortedBoxes[PRE_NMS + 64];
__device__ __align__(16) u64 g_mask1024[MCH * MWORDS];
__device__ u32    g_barCount;
__device__ u32    g_barGen;

// ---------------- helpers ----------------
__device__ __forceinline__ u32 flip_score(float s) {
    u32 u = __float_as_uint(s);
    return (u & 0x80000000u) ? ~u : (u | 0x80000000u);
}

__device__ __forceinline__ float4 decode_box(const float* __restrict__ deltas,
                                             const float* __restrict__ anchors,
                                             int i) {
    float4 a = reinterpret_cast<const float4*>(anchors)[i];
    float4 d = reinterpret_cast<const float4*>(deltas)[i];
    float h = a.z - a.x;
    float w = a.w - a.y;
    float cy = a.x + 0.5f * h;
    float cx = a.y + 0.5f * w;
    float ncy = d.x * h + cy;
    float ncx = d.y * w + cx;
    float nh = expf(d.z) * h;
    float nw = expf(d.w) * w;
    float ymin = fminf(fmaxf(ncy - 0.5f * nh, 0.0f), IMG_H);
    float xmin = fminf(fmaxf(ncx - 0.5f * nw, 0.0f), IMG_W);
    float ymax = fminf(fmaxf(ncy + 0.5f * nh, 0.0f), IMG_H);
    float xmax = fminf(fmaxf(ncx + 0.5f * nw, 0.0f), IMG_W);
    return make_float4(ymin, xmin, ymax, xmax);
}

// software grid barrier: safe because all GRID blocks are guaranteed co-resident
__device__ __forceinline__ void grid_bar(u32 target) {
    __syncthreads();
    if (threadIdx.x == 0) {
        __threadfence();
        u32 old = atomicAdd(&g_barCount, 1u);
        if (old == GRID - 1u) {
            g_barCount = 0u;
            __threadfence();
            atomicExch(&g_barGen, target);
        } else {
            u32 cur;
            for (;;) {
                asm volatile("ld.acquire.gpu.u32 %0, [%1];" : "=r"(cur) : "l"(&g_barGen) : "memory");
                if (cur >= target) break;
                __nanosleep(64);
            }
        }
        __threadfence();
    }
    __syncthreads();
}

// ---------------- the one kernel ----------------
__global__ void __launch_bounds__(BLK, 1)
rpn_all(const float* __restrict__ deltas,
        const float* __restrict__ anchors,
        const float* __restrict__ scores,
        float* __restrict__ out, int N) {
    __shared__ float4 sBox[MCH];          // mask phase
    __shared__ float  sArea[MCH];
    __shared__ u32    ssum[1024];         // threshold phase
    __shared__ u32    sCnt, sBase;        // compact phase
    __shared__ u32    sNz32[BLK / 32];    // scan phase
    __shared__ u64    sKeptMask[MWORDS];
    __shared__ u32    sKeptBase[MWORDS];
    __shared__ int    sKept;
    __shared__ float4 kb[POST_NMS];
    __shared__ float  karea[POST_NMS];

    const int t   = threadIdx.x;
    const int gid = blockIdx.x * BLK + t;

    // ===== Phase A: decode + valid + flipped score + 16-bit histogram =====
    for (int i = gid; i < N; i += NTHREADS) {
        float4 b = decode_box(deltas, anchors, i);
        bool valid = ((b.z - b.x) >= STRIDE_F) && ((b.w - b.y) >= STRIDE_F);
        u32 s = 0u;
        if (valid) {
            s = flip_score(scores[i]);
            atomicAdd(&g_hist[s >> 16], 1u);
        }
        g_score32[i] = s;
    }
    grid_bar(1);

    // ===== Phase B: threshold (block 0), with hist re-zero =====
    if (blockIdx.x == 0) {
        u32 sum = 0;
        const uint4* h4 = reinterpret_cast<const uint4*>(&g_hist[t << 6]);
        #pragma unroll
        for (int b = 0; b < 16; b++) { uint4 v = h4[b]; sum += v.x + v.y + v.z + v.w; }
        ssum[t] = sum;
        __syncthreads();
        for (int off = 1; off < 1024; off <<= 1) {
            u32 v = (t + off < 1024) ? ssum[t + off] : 0u;
            __syncthreads();
            ssum[t] += v;
            __syncthreads();
        }
        u32 myCum = ssum[t];
        u32 nxtCum = (t < 1023) ? ssum[t + 1] : 0u;
        if (myCum >= PRE_NMS && nxtCum < PRE_NMS) {
            u32 running = nxtCum;
            for (int b = 63; b >= 0; b--) {
                running += g_hist[(t << 6) + b];
                if (running >= PRE_NMS) { g_t16 = (u32)((t << 6) + b); break; }
            }
        }
        if (t == 0 && ssum[0] < PRE_NMS) g_t16 = 0u;
        __syncthreads();
        #pragma unroll
        for (int k = 0; k < 64; k++) g_hist[t + (k << 10)] = 0u;
    }
    grid_bar(2);

    // ===== Phase C: compact candidates (block-aggregated atomics) =====
    {
        if (t == 0) sCnt = 0u;
        __syncthreads();
        u32 keyS[2]; int keyI[2]; u32 npass = 0;
        for (int i = gid; i < N; i += NTHREADS) {
            u32 s = g_score32[i];
            if (s != 0u && (s >> 16) >= g_t16) { keyS[npass] = s; keyI[npass] = i; npass++; }
        }
        u32 local = npass ? atomicAdd(&sCnt, npass) : 0u;
        __syncthreads();
        if (t == 0) sBase = (sCnt > 0u) ? atomicAdd(&g_candCount, sCnt) : 0u;
        __syncthreads();
        for (u32 k = 0; k < npass; k++) {
            u32 pos = sBase + local + k;
            if (pos < CAP) g_cand[pos] = ((u64)keyS[k] << 32) | (u32)(~(u32)keyI[k]);
        }
    }
    grid_bar(3);

    // ===== Phase D: exact rank by counting (warp per row, no atomics) =====
    {
        int C = min((int)g_candCount, CAP);
        int gw = gid >> 5;
        int lane = t & 31;
        for (int r = gw; r < C; r += NWARPS) {
            u64 myKey = __ldg(&g_cand[r]);
            int cnt = 0;
            int c = lane;
            for (; c + 96 < C; c += 128) {
                u64 k0 = __ldg(&g_cand[c]);
                u64 k1 = __ldg(&g_cand[c + 32]);
                u64 k2 = __ldg(&g_cand[c + 64]);
                u64 k3 = __ldg(&g_cand[c + 96]);
                cnt += (k0 > myKey) + (k1 > myKey) + (k2 > myKey) + (k3 > myKey);
            }
            for (; c < C; c += 32) cnt += (__ldg(&g_cand[c]) > myKey);
            #pragma unroll
            for (int off = 16; off > 0; off >>= 1)
                cnt += __shfl_down_sync(0xffffffffu, cnt, off);
            if (lane == 0) g_rank[r] = (u32)cnt;
        }
    }
    grid_bar(4);

    // ===== Phase E: scatter (recompute decode for candidates only) =====
    {
        int C = min((int)g_candCount, CAP);
        for (int i = gid; i < C; i += NTHREADS) {
            u32 rank = g_rank[i];
            if (rank < PRE_NMS) {
                u64 key = g_cand[i];
                int idx = (int)(~(u32)(key & 0xFFFFFFFFull));
                g_sortedBoxes[rank] = decode_box(deltas, anchors, idx);
            }
        }
    }
    grid_bar(5);

    // ===== Phase F: suppression bitmask over first MCH (blocks 0..15) =====
    {
        int n = min((int)g_candCount, PRE_NMS);
        if (blockIdx.x < 16) {
            float4 b = (blockIdx.x * 64 + 0, t < MCH) ? make_float4(0.f,0.f,0.f,0.f) : make_float4(0.f,0.f,0.f,0.f);
            // stage first MCH boxes
            {
                float4 v = (t < n && t < MCH) ? g_sortedBoxes[t] : make_float4(0.f, 0.f, 0.f, 0.f);
                sBox[t] = v;
                sArea[t] = (v.z - v.x) * (v.w - v.y);
            }
            __syncthreads();
            int r = t & 63;
            int w = t >> 6;
            int i = blockIdx.x * 64 + r;
            u64 word = 0ull;
            int j0 = w << 6;
            if (i < n && (j0 + 63) > i) {
                float4 bi = sBox[i];
                float  ai = sArea[i];
                #pragma unroll 8
                for (int bb = 0; bb < 64; bb++) {
                    int j = j0 + bb;
                    float4 bj = sBox[j];
                    float  aj = sArea[j];
                    float iy = fmaxf(0.0f, fminf(bi.z, bj.z) - fmaxf(bi.x, bj.x));
                    float ix = fmaxf(0.0f, fminf(bi.w, bj.w) - fmaxf(bi.y, bj.y));
                    float inter = iy * ix;
                    float iou = inter / (ai + aj - inter + 1e-9f);
                    if (iou > IOU_THR && j > i) word |= (1ull << bb);
                }
            }
            g_mask1024[(size_t)i * MWORDS + w] = word;
        }
    }
    grid_bar(6);

    // ===== Phase G: scan + write-out (block 0 only) =====
    if (blockIdx.x != 0) return;
    {
        int n = min((int)g_candCount, PRE_NMS);
        int m = min(n, MCH);

        if (t < MWORDS) { sKeptMask[t] = 0ull; sKeptBase[t] = 0u; }
        // nonzero-row flags via ballot (j = t)
        {
            bool nzRow = false;
            if (t < m) {
                const u64* row = &g_mask1024[(size_t)t * MWORDS];
                u64 o = 0ull;
                #pragma unroll
                for (int k = 0; k < MWORDS; k++) o |= row[k];
                nzRow = (o != 0ull);
            }
            u32 b = __ballot_sync(0xffffffffu, nzRow);
            if ((t & 31) == 0) sNz32[t >> 5] = b;
        }
        __syncthreads();

        if (t == 0) {
            u64 rem[MWORDS];
            #pragma unroll
            for (int k = 0; k < MWORDS; k++) rem[k] = 0ull;
            int kept = 0;
            int nw = (m + 63) >> 6;
            for (int wd = 0; wd < nw && kept < POST_NMS; wd++) {
                int nb = min(64, m - (wd << 6));
                u64 nz = (u64)sNz32[wd * 2] | ((u64)sNz32[wd * 2 + 1] << 32);
                u64 bad = rem[wd] | nz;
                u64 kmask;
                sKeptBase[wd] = (u32)kept;
                if (bad == 0ull && kept + nb <= POST_NMS) {
                    kmask = (nb == 64) ? ~0ull : ((1ull << nb) - 1ull);
                    kept += nb;
                } else {
                    kmask = 0ull;
                    for (int b = 0; b < nb && kept < POST_NMS; b++) {
                        if (!((rem[wd] >> b) & 1ull)) {
                            kmask |= (1ull << b);
                            kept++;
                            if ((nz >> b) & 1ull) {
                                const u64* row = &g_mask1024[(size_t)((wd << 6) + b) * MWORDS];
                                #pragma unroll
                                for (int k = 0; k < MWORDS; k++) rem[k] |= row[k];
                            }
                        }
                    }
                }
                sKeptMask[wd] = kmask;
            }
            sKept = kept;
        }
        __syncthreads();
        int kept = sKept;

        // tail zeros + kept expansion
        for (int k = t; k < POST_NMS; k += BLK)
            if (k >= kept) reinterpret_cast<float4*>(out)[k] = make_float4(0.f, 0.f, 0.f, 0.f);
        for (int j = t; j < m; j += BLK) {
            int wd = j >> 6, b = j & 63;
            u64 km = sKeptMask[wd];
            if ((km >> b) & 1ull) {
                u64 below = (b == 0) ? 0ull : (km & ((1ull << b) - 1ull));
                int slot = (int)sKeptBase[wd] + __popcll(below);
                if (slot < POST_NMS)
                    reinterpret_cast<float4*>(out)[slot] = g_sortedBoxes[j];
            }
        }

        // fallback (rare): continue incrementally past MCH
        if (kept < POST_NMS && n > m) {
            __syncthreads();
            for (int k = t; k < kept; k += BLK) {
                float4 b = reinterpret_cast<float4*>(out)[k];
                kb[k] = b;
                karea[k] = (b.z - b.x) * (b.w - b.y);
            }
            __syncthreads();
            for (int i = m; i < n; i++) {
                float4 b = g_sortedBoxes[i];
                float  ab = (b.z - b.x) * (b.w - b.y);
                bool sup = false;
                for (int k = t; k < kept; k += BLK) {
                    float4 c  = kb[k];
                    float  ac = karea[k];
                    float iy = fmaxf(0.0f, fminf(b.z, c.z) - fmaxf(b.x, c.x));
                    float ix = fmaxf(0.0f, fminf(b.w, c.w) - fmaxf(b.y, c.y));
                    float inter = iy * ix;
                    float iou = inter / (ab + ac - inter + 1e-9f);
                    sup = sup || (iou > IOU_THR);
                }
                int any = __syncthreads_or((int)sup);
                if (!any) {
                    if (t == 0) {
                        kb[kept]    = b;
                        karea[kept] = ab;
                        reinterpret_cast<float4*>(out)[kept] = b;
                    }
                    kept++;
                    if (kept >= POST_NMS) break;
                    __syncthreads();
                }
            }
        }

        // reset per-run scratch
        __syncthreads();
        if (t == 0) {
            g_candCount = 0u;
            __threadfence();
            g_barGen = 0u;
        }
    }
}

// ---------------- launch ----------------
extern "C" void kernel_launch(void* const* d_in, const int* in_sizes, int n_in,
                              void* d_out, int out_size) {
    const float* deltas  = (const float*)d_in[0];
    const float* anchors = (const float*)d_in[1];
    const float* scores  = (const float*)d_in[2];
    int N = in_sizes[2];
    if (N > NMAX) N = NMAX;
    float* out = (float*)d_out;
    rpn_all<<<GRID, BLK>>>(deltas, anchors, scores, out, N);
}